// round 9
// baseline (speedup 1.0000x reference)
#include <cuda_runtime.h>

// grid [2,160,160,160,3] float32
#define BB 2
#define NX 160
#define NY 160
#define NZ 160

#define TY 12
#define NCHUNK 6                  // z chunks, 28 outputs each (168 >= 156)
#define XSPLIT 12
#define XSTEPS 13                 // 156 / XSPLIT
#define NTHREADS (TY*32)          // 384
#define NBLOCKS (NCHUNK*13*BB*XSPLIT) // 1872

#define RY (TY + 4)               // 16
#define RZ_ST 32                  // staged z per slice
#define SLICE (RY * RZ_ST * 3)    // 1536 floats
#define ROWW (NZ * 3)             // 480 floats per (b,x,y) row
#define CPR (RZ_ST * 3 / 4)       // 24 16B chunks per staged row

__device__ double g_be_sum;
__device__ unsigned int g_be_cnt;

__device__ __forceinline__ void cp16(unsigned int dst_smem, const float* src) {
    asm volatile("cp.async.cg.shared.global [%0], [%1], 16;" :: "r"(dst_smem), "l"(src));
}
__device__ __forceinline__ void cp_commit() {
    asm volatile("cp.async.commit_group;" ::: "memory");
}
__device__ __forceinline__ void cp_wait0() {
    asm volatile("cp.async.wait_group 0;" ::: "memory");
}
__device__ __forceinline__ void cp_wait1() {
    asm volatile("cp.async.wait_group 1;" ::: "memory");
}

#define SHUP(v)  __shfl_up_sync(0xffffffffu, (v), 1)
#define SHDN(v)  __shfl_down_sync(0xffffffffu, (v), 1)
#define SHUP2(v) __shfl_up_sync(0xffffffffu, (v), 2)
#define SHDN2(v) __shfl_down_sync(0xffffffffu, (v), 2)

__global__ __launch_bounds__(NTHREADS, 3)
void be_main_kernel(const float* __restrict__ g, float* __restrict__ out) {
    __shared__ float ring[4 * SLICE];       // read set {x+2} only -> 4 slots suffice
    __shared__ float warp_part[NTHREADS / 32];

    const int tz  = threadIdx.x;            // 0..31 (lane)
    const int ty  = threadIdx.y;            // 0..11
    const int tid = ty * 32 + tz;

    const int cz  = blockIdx.x;             // 0..5   z chunk (28 outputs each)
    const int cy  = blockIdx.y;             // 0..12
    const int b   = blockIdx.z / XSPLIT;
    const int seg = blockIdx.z % XSPLIT;

    const int z0 = 2 + cz * 28;
    const int y0 = 2 + cy * TY;
    const int xs = 2 + seg * XSTEPS;

    const int zc = z0 - 2 + tz;
    const bool active = (tz >= 2) && (tz <= 29) && (zc <= NZ - 3);

    // ---- staging map: exactly one 16B chunk per thread ----
    const int zbase3 = (z0 - 2) * 3;
    int goff;
    {
        int row = tid / CPR, col = tid - row * CPR;
        int o = zbase3 + col * 4;
        if (o > ROWW - 4) o = ROWW - 4;     // clamp: lands in unread lane-halo slack
        goff = row * ROWW + o;
    }

    const long long bbase = (long long)b * NX * NY * ROWW + (long long)(y0 - 2) * ROWW;
    const unsigned int ring_s = (unsigned int)__cvta_generic_to_shared(ring);

    auto issue_slice = [&](int gx, int slot) {
        const float* src = g + bbase + (long long)gx * (NY * ROWW);
        cp16(ring_s + (unsigned int)(slot * SLICE) * 4u + (unsigned int)tid * 16u,
             src + goff);
    };

    // ---- slot(gx) = (gx - xs + 2) mod 4; prologue: xs-2..xs+1 -> slots 0..3 ----
    issue_slice(xs - 2, 0);
    issue_slice(xs - 1, 1);
    issue_slice(xs,     2);
    issue_slice(xs + 1, 3);
    cp_commit();
    cp_wait0();
    __syncthreads();

    const int off0 = ((ty + 2) * RZ_ST + tz) * 3;
    #define Y (RZ_ST * 3)

    // delay lines
    float c0a, c0b, c0c, c0d, c0e;          // comp0 centers x+1..x-2 (+junk)
    float c1p2, c1p1, c1z;                  // comp1 centers x+1, x, x-1
    float c2p2, c2p1, c2z;                  // comp2
    float qa0, qa1, qa2, qb0, qb1, qb2, qc0, qc1, qc2;  // q_xy at x+1, x, x-1
    float syA0, syA1, syB0, syB1;           // y-sums (c0,c1) for slices x, x+1
    {
        const float* s;
        s = ring + 3 * SLICE;               // xs+1
        c0a = s[off0]; c1p2 = s[off0 + 1]; c2p2 = s[off0 + 2];
        qa0 = s[off0 + Y]     - s[off0 - Y];
        qa1 = s[off0 + Y + 1] - s[off0 - Y + 1];
        qa2 = s[off0 + Y + 2] - s[off0 - Y + 2];
        syB0 = s[off0 + 2*Y]     + s[off0 - 2*Y];
        syB1 = s[off0 + 2*Y + 1] + s[off0 - 2*Y + 1];
        s = ring + 2 * SLICE;               // xs
        c0b = s[off0]; c1p1 = s[off0 + 1]; c2p1 = s[off0 + 2];
        qb0 = s[off0 + Y]     - s[off0 - Y];
        qb1 = s[off0 + Y + 1] - s[off0 - Y + 1];
        qb2 = s[off0 + Y + 2] - s[off0 - Y + 2];
        syA0 = s[off0 + 2*Y]     + s[off0 - 2*Y];
        syA1 = s[off0 + 2*Y + 1] + s[off0 - 2*Y + 1];
        s = ring + 1 * SLICE;               // xs-1
        c0c = s[off0]; c1z = s[off0 + 1]; c2z = s[off0 + 2];
        qc0 = s[off0 + Y]     - s[off0 - Y];
        qc1 = s[off0 + Y + 1] - s[off0 - Y + 1];
        qc2 = s[off0 + Y + 2] - s[off0 - Y + 2];
        s = ring;                           // xs-2
        c0d = s[off0];
        c0e = 0.f;
    }
    __syncthreads();            // init reads done before slot reuse

    // pipeline: xs+2 -> slot 0, xs+3 -> slot 1 (two groups in flight)
    issue_slice(xs + 2, 0); cp_commit();
    issue_slice(xs + 3, 1); cp_commit();

    float acc = 0.0f;
    int gx4 = xs + 4;

    // step i: SP2 slot = i%4 (slice x+2), STG slot = (i+2)%4 (stage x+4, held x, dead)
    #define DO_STEP(STGi, SP2i)                                                   \
    {                                                                             \
        cp_wait1();                                                               \
        __syncthreads();                                                          \
        {                                                                         \
            int gxs = gx4 > (NX - 1) ? (NX - 1) : gx4;                            \
            issue_slice(gxs, (STGi)); cp_commit(); ++gx4;                         \
        }                                                                         \
        const float* Sp = ring + (SP2i) * SLICE;  /* slice x+2 (fresh) */         \
        const float n0 = Sp[off0], n1 = Sp[off0 + 1], n2 = Sp[off0 + 2];          \
        const float qf0 = Sp[off0 + Y]     - Sp[off0 - Y];                        \
        const float qf1 = Sp[off0 + Y + 1] - Sp[off0 - Y + 1];                    \
        const float qf2 = Sp[off0 + Y + 2] - Sp[off0 - Y + 2];                    \
        const float g0  = Sp[off0 + 2*Y]     + Sp[off0 - 2*Y];                    \
        const float g1  = Sp[off0 + 2*Y + 1] + Sp[off0 - 2*Y + 1];                \
        const float c1m = c1z, c2m = c2z;         /* x-1 comps 1,2 */             \
        c0e = c0d; c0d = c0c; c0c = c0b; c0b = c0a; c0a = n0;                     \
        c1z = c1p1; c1p1 = c1p2; c1p2 = n1;       /* c1z -> x */                  \
        c2z = c2p1; c2p1 = c2p2; c2p2 = n2;                                       \
        const float d0 = c0b - c0d, d1 = c1p1 - c1m, d2 = c2p1 - c2m;             \
        const float dxz0 = SHDN(d0) - SHUP(d0);                                   \
        const float dxz1 = SHDN(d1) - SHUP(d1);                                   \
        const float dxz2 = SHDN(d2) - SHUP(d2);                                   \
        const float dyz0 = SHDN(qb0) - SHUP(qb0);                                 \
        const float dyz1 = SHDN(qb1) - SHUP(qb1);                                 \
        const float dyz2 = SHDN(qb2) - SHUP(qb2);                                 \
        const float dzz0 = SHUP2(c0c) + SHDN2(c0c) - 2.0f * c0c;                  \
        const float dzz1 = SHUP2(c1z) + SHDN2(c1z) - 2.0f * c1z;                  \
        const float dzz2 = SHUP2(c2z) + SHDN2(c2z) - 2.0f * c2z;                  \
        if (active) {                                                             \
            const float dxx0 = c0e + c0a - 2.0f * c0c;                            \
            const float dyy0 = syA0 - 2.0f * c0c;                                 \
            const float dyy1 = syA1 - 2.0f * c1z;                                 \
            const float dxy0 = qa0 - qc0;                                         \
            const float dxy1 = qa1 - qc1;                                         \
            float v = dxx0 * dxx0;                                                \
            v = fmaf(2.0f * dyy0, dyy0, v);                                       \
            v = fmaf(2.0f * dzz0, dzz0, v);                                       \
            v = fmaf(3.0f * dxy0, dxy0, v);                                       \
            v = fmaf(3.0f * dxz0, dxz0, v);                                       \
            v = fmaf(4.0f * dyz0, dyz0, v);                                       \
            v = fmaf(dyy1, dyy1, v);                                              \
            v = fmaf(2.0f * dzz1, dzz1, v);                                       \
            v = fmaf(dxy1, dxy1, v);                                              \
            v = fmaf(2.0f * dxz1, dxz1, v);                                       \
            v = fmaf(3.0f * dyz1, dyz1, v);                                       \
            v = fmaf(dzz2, dzz2, v);                                              \
            v = fmaf(dxz2, dxz2, v);                                              \
            v = fmaf(dyz2, dyz2, v);                                              \
            acc += v;                                                             \
        }                                                                         \
        qc0 = qb0; qc1 = qb1; qc2 = qb2;                                          \
        qb0 = qa0; qb1 = qa1; qb2 = qa2;                                          \
        qa0 = qf0; qa1 = qf1; qa2 = qf2;                                          \
        syA0 = syB0; syA1 = syB1; syB0 = g0; syB1 = g1;                           \
    }

    // 13 steps = 3 x 4 + 1; slot pattern period 4 (all literals)
    #pragma unroll 1
    for (int it = 0; it < 3; ++it) {
        DO_STEP(2, 0);
        DO_STEP(3, 1);
        DO_STEP(0, 2);
        DO_STEP(1, 3);
    }
    DO_STEP(2, 0);              // step 12

    #undef DO_STEP
    #undef Y

    // block reduction
    float v = acc;
    #pragma unroll
    for (int o = 16; o > 0; o >>= 1) v += __shfl_down_sync(0xffffffffu, v, o);
    if ((tid & 31) == 0) warp_part[tid >> 5] = v;
    __syncthreads();
    if (tid == 0) {
        float s = 0.0f;
        #pragma unroll
        for (int w = 0; w < NTHREADS / 32; ++w) s += warp_part[w];
        atomicAdd(&g_be_sum, (double)s);
        __threadfence();
        unsigned int t = atomicAdd(&g_be_cnt, 1u);
        if (t == NBLOCKS - 1) {
            double total = atomicAdd(&g_be_sum, 0.0);   // ordered read of final sum
            const double n = (double)BB * 156.0 * 156.0 * 156.0 * 3.0;
            out[0] = (float)(total / (16.0 * n));
            g_be_cnt = 0;        // reset for next (graph-replayed) launch
            g_be_sum = 0.0;
        }
    }
}

extern "C" void kernel_launch(void* const* d_in, const int* in_sizes, int n_in,
                              void* d_out, int out_size) {
    const float* grid = (const float*)d_in[0];
    float* out = (float*)d_out;

    dim3 blk(32, TY, 1);
    dim3 grd(NCHUNK, 13, BB * XSPLIT);
    be_main_kernel<<<grd, blk>>>(grid, out);
}